// round 1
// baseline (speedup 1.0000x reference)
#include <cuda_runtime.h>

#define B_ 4
#define C_ 32
#define H_ 512
#define W_ 512

// ---------------- scratch (device globals; no runtime allocation) ----------------
static __device__ float g_op[(size_t)B_ * 160 * H_ * W_];   // pre-norm operator output (671MB)
static __device__ float g_t1[(size_t)B_ * C_ * H_ * W_];    // 512x512 feature map
static __device__ float g_s1[(size_t)B_ * C_ * 256 * 256];
static __device__ float g_s2[(size_t)B_ * C_ * 256 * 256];
static __device__ float g_q1[(size_t)B_ * C_ * 128 * 128];
static __device__ float g_q2[(size_t)B_ * C_ * 128 * 128];
static __device__ float g_e1[(size_t)B_ * C_ * 64 * 64];
static __device__ float g_e2[(size_t)B_ * C_ * 64 * 64];
static __device__ float g_part[20 * 64 * 2];                // stage-1 partial sums
static __device__ float g_norm[40];                         // (mean, inv_std) per (b, branch)

// ---------------- operator kernel: 5 edge filters, reflect-101 padding ----------------
// grid: (W/32, H/8, B*C), block: (32, 8)
__global__ void op_kernel(const float* __restrict__ x) {
    __shared__ float sx[10][34];
    const int tx = threadIdx.x, ty = threadIdx.y;
    const int tid = ty * 32 + tx;
    const int w0 = blockIdx.x * 32, h0 = blockIdx.y * 8;
    const int bc = blockIdx.z;                  // b*32 + c
    const int b = bc >> 5, c = bc & 31;
    const float* xp = x + (size_t)bc * H_ * W_;

    for (int i = tid; i < 340; i += 256) {
        int r = i / 34, cl = i % 34;
        int hh = h0 - 1 + r;
        hh = hh < 0 ? -hh : (hh >= H_ ? 2 * H_ - 2 - hh : hh);
        int ww = w0 - 1 + cl;
        ww = ww < 0 ? -ww : (ww >= W_ ? 2 * W_ - 2 - ww : ww);
        sx[r][cl] = xp[hh * W_ + ww];
    }
    __syncthreads();

    const float a00 = sx[ty + 0][tx + 0], a01 = sx[ty + 0][tx + 1], a02 = sx[ty + 0][tx + 2];
    const float a10 = sx[ty + 1][tx + 0], a11 = sx[ty + 1][tx + 1], a12 = sx[ty + 1][tx + 2];
    const float a20 = sx[ty + 2][tx + 0], a21 = sx[ty + 2][tx + 1], a22 = sx[ty + 2][tx + 2];

    // Sobel
    float sxv = -a00 + a02 - 2.f * a10 + 2.f * a12 - a20 + a22;
    float syv = -a00 - 2.f * a01 - a02 + a20 + 2.f * a21 + a22;
    float b1 = 0.5f * (sxv + syv);
    // Scharr
    float cxv = -3.f * a00 + 3.f * a02 - 10.f * a10 + 10.f * a12 - 3.f * a20 + 3.f * a22;
    float cyv = -3.f * a00 - 10.f * a01 - 3.f * a02 + 3.f * a20 + 10.f * a21 + 3.f * a22;
    float b2 = 0.5f * (cxv + cyv);
    // Laplace (cv2 ksize=3)
    float b3 = 2.f * a00 + 2.f * a02 - 8.f * a11 + 2.f * a20 + 2.f * a22;
    // Roberts, pad ((1,0),(1,0)): rx = -x[h-1,w-1]+x[h,w], ry = -x[h-1,w]+x[h,w-1]
    float b4 = 0.5f * ((-a00 + a11) + (-a01 + a10));
    // Prewitt
    float pxv = a00 + a01 + a02 - a20 - a21 - a22;
    float pyv = -a00 + a02 - a10 + a12 - a20 + a22;
    float b5 = 0.5f * (pxv + pyv);

    const size_t BR = (size_t)32 * H_ * W_;
    size_t base = (((size_t)b * 160 + c) * H_ + (h0 + ty)) * W_ + (w0 + tx);
    g_op[base + 0 * BR] = b1;
    g_op[base + 1 * BR] = b2;
    g_op[base + 2 * BR] = b3;
    g_op[base + 3 * BR] = b4;
    g_op[base + 4 * BR] = b5;
}

// ---------------- stats: deterministic two-stage reduction ----------------
// stage 1: grid 20*64 blocks, 256 threads; each block reduces 131072 elements
__global__ void stats1_kernel() {
    const int seg = blockIdx.x >> 6;   // 0..19 = b*5 + branch
    const int part = blockIdx.x & 63;
    const int b = seg / 5, br = seg % 5;
    const float4* p = (const float4*)(g_op + ((size_t)b * 160 + (size_t)br * 32) * H_ * W_)
                      + (size_t)part * 32768;
    float s = 0.f, q = 0.f;
    for (int i = threadIdx.x; i < 32768; i += 256) {
        float4 v = p[i];
        s += v.x + v.y + v.z + v.w;
        q += v.x * v.x + v.y * v.y + v.z * v.z + v.w * v.w;
    }
    __shared__ float rs[256], rq[256];
    rs[threadIdx.x] = s; rq[threadIdx.x] = q;
    __syncthreads();
    for (int st = 128; st > 0; st >>= 1) {
        if (threadIdx.x < st) { rs[threadIdx.x] += rs[threadIdx.x + st]; rq[threadIdx.x] += rq[threadIdx.x + st]; }
        __syncthreads();
    }
    if (threadIdx.x == 0) {
        g_part[blockIdx.x * 2 + 0] = rs[0];
        g_part[blockIdx.x * 2 + 1] = rq[0];
    }
}

// stage 2: grid 20 blocks, 64 threads
__global__ void stats2_kernel() {
    __shared__ float rs[64], rq[64];
    const int seg = blockIdx.x, t = threadIdx.x;
    rs[t] = g_part[(seg * 64 + t) * 2 + 0];
    rq[t] = g_part[(seg * 64 + t) * 2 + 1];
    __syncthreads();
    for (int st = 32; st > 0; st >>= 1) {
        if (t < st) { rs[t] += rs[t + st]; rq[t] += rq[t + st]; }
        __syncthreads();
    }
    if (t == 0) {
        const double N = (double)32 * H_ * W_;
        double mean = (double)rs[0] / N;
        double var = (double)rq[0] / N - mean * mean;
        if (var < 1e-30) var = 1e-30;
        g_norm[seg * 2 + 0] = (float)mean;
        g_norm[seg * 2 + 1] = (float)(1.0 / sqrt(var));
    }
}

// ---------------- conv3x3 (zero pad), all 32 out channels per thread ----------------
// MODE 0: plain; MODE 1: normalize input inline (conv1 over g_op); MODE 2: fuse orig*y epilogue
// grid: (W/32, H/8, B), block: (32, 8)
template <int CIN, int MODE>
__global__ void conv3x3_kernel(const float* __restrict__ in, const float* __restrict__ wgt,
                               const float* __restrict__ bias, float* __restrict__ out,
                               int Hh, int Ww, const float* __restrict__ orig) {
    __shared__ float s_in[4 * 340];    // 4 ci x (10 x 34)
    __shared__ float s_w[4 * 288];     // 4 ci x (9 taps x 32 co)
    __shared__ float s_nm[5], s_ns[5];

    const int tx = threadIdx.x, ty = threadIdx.y;
    const int tid = ty * 32 + tx;
    const int w0 = blockIdx.x * 32, h0 = blockIdx.y * 8;
    const int b = blockIdx.z;

    if (MODE == 1 && tid < 5) {
        s_nm[tid] = g_norm[(b * 5 + tid) * 2 + 0];
        s_ns[tid] = g_norm[(b * 5 + tid) * 2 + 1];
    }

    float acc[32];
#pragma unroll
    for (int co = 0; co < 32; ++co) acc[co] = bias[co];

    for (int ci0 = 0; ci0 < CIN; ci0 += 4) {
        __syncthreads();
        // weights: s_w[cc*288 + tap*32 + co]
        for (int i = tid; i < 1152; i += 256) {
            int cc = i / 288, rem = i % 288;
            int tap = rem >> 5, co = rem & 31;
            s_w[i] = wgt[((size_t)co * CIN + (ci0 + cc)) * 9 + tap];
        }
        // input tile: s_in[cc*340 + r*34 + c]
        for (int i = tid; i < 1360; i += 256) {
            int cc = i / 340, rem = i % 340;
            int r = rem / 34, cl = rem % 34;
            int hh = h0 - 1 + r, ww = w0 - 1 + cl;
            float v = 0.f;
            if (hh >= 0 && hh < Hh && ww >= 0 && ww < Ww) {
                v = in[(((size_t)b * CIN + (ci0 + cc)) * Hh + hh) * Ww + ww];
                if (MODE == 1) {
                    int br = (ci0 + cc) >> 5;
                    v = (v - s_nm[br]) * s_ns[br];
                }
            }
            s_in[i] = v;
        }
        __syncthreads();

#pragma unroll
        for (int cc = 0; cc < 4; ++cc) {
            float v[9];
#pragma unroll
            for (int t = 0; t < 9; ++t)
                v[t] = s_in[cc * 340 + (ty + t / 3) * 34 + (tx + t % 3)];
#pragma unroll
            for (int t = 0; t < 9; ++t) {
                const float4* wp = (const float4*)(s_w + cc * 288 + t * 32);
#pragma unroll
                for (int j = 0; j < 8; ++j) {
                    float4 w4 = wp[j];
                    acc[j * 4 + 0] += v[t] * w4.x;
                    acc[j * 4 + 1] += v[t] * w4.y;
                    acc[j * 4 + 2] += v[t] * w4.z;
                    acc[j * 4 + 3] += v[t] * w4.w;
                }
            }
        }
    }

    const int h = h0 + ty, w = w0 + tx;
    const size_t plane = (size_t)Hh * Ww;
    size_t obase = ((size_t)b * 32) * plane + (size_t)h * Ww + w;
#pragma unroll
    for (int co = 0; co < 32; ++co) {
        float r = acc[co];
        if (MODE == 2) r *= orig[obase + (size_t)co * plane];
        out[obase + (size_t)co * plane] = r;
    }
}

// ---------------- 2x2 max pool (Hh, Ww = OUTPUT dims) ----------------
__global__ void maxpool_kernel(const float* __restrict__ in, float* __restrict__ out,
                               int Hh, int Ww) {
    size_t n = (size_t)blockIdx.x * 256 + threadIdx.x;
    size_t total = (size_t)B_ * 32 * Hh * Ww;
    if (n >= total) return;
    int w = (int)(n % Ww);
    size_t r = n / Ww;
    int h = (int)(r % Hh);
    size_t bc = r / Hh;
    const float* p = in + (bc * (2 * (size_t)Hh) + 2 * h) * (2 * (size_t)Ww) + 2 * w;
    float m = fmaxf(fmaxf(p[0], p[1]), fmaxf(p[2 * Ww], p[2 * Ww + 1]));
    out[n] = m;
}

// ---------------- deconv 2x2 stride 2 ----------------
// grid: (Wi/32, 4, B*Hi), block: (32, 8)  (tx = w, ty = local out channel)
__global__ void deconv_kernel(const float* __restrict__ in, const float* __restrict__ wgt,
                              const float* __restrict__ bias, float* __restrict__ out,
                              int Hi, int Wi) {
    __shared__ float sx[32][33];       // [ci][w]
    __shared__ float sw[32][8][4];     // [ci][o_local][pq]
    const int tx = threadIdx.x, ty = threadIdx.y;
    const int tid = ty * 32 + tx;
    const int w0 = blockIdx.x * 32;
    const int oc0 = blockIdx.y * 8;
    const int bh = blockIdx.z;
    const int b = bh / Hi, h = bh % Hi;

    for (int i = tid; i < 1024; i += 256) {
        int ci = i >> 5, w = i & 31;
        sx[ci][w] = in[(((size_t)b * 32 + ci) * Hi + h) * Wi + (w0 + w)];
    }
    for (int i = tid; i < 1024; i += 256) {
        int ci = i >> 5, rem = i & 31;
        int ol = rem >> 2, pq = rem & 3;
        sw[ci][ol][pq] = wgt[(size_t)ci * 128 + (oc0 + ol) * 4 + pq];
    }
    __syncthreads();

    const int o = oc0 + ty;
    const float bv = bias[o];
    float a0 = bv, a1 = bv, a2 = bv, a3 = bv;
#pragma unroll
    for (int ci = 0; ci < 32; ++ci) {
        float v = sx[ci][tx];
        a0 += v * sw[ci][ty][0];
        a1 += v * sw[ci][ty][1];
        a2 += v * sw[ci][ty][2];
        a3 += v * sw[ci][ty][3];
    }
    const int Ho = 2 * Hi, Wo = 2 * Wi;
    size_t ob = (((size_t)b * 32 + o) * Ho + 2 * h) * (size_t)Wo + 2 * (w0 + tx);
    *(float2*)(out + ob) = make_float2(a0, a1);
    *(float2*)(out + ob + Wo) = make_float2(a2, a3);
}

// ---------------- host launch ----------------
extern "C" void kernel_launch(void* const* d_in, const int* in_sizes, int n_in,
                              void* d_out, int out_size) {
    const float* x = (const float*)d_in[0];
    const float* w1 = (const float*)d_in[1];   const float* b1 = (const float*)d_in[2];
    const float* w2 = (const float*)d_in[3];   const float* b2 = (const float*)d_in[4];
    const float* w3 = (const float*)d_in[5];   const float* b3 = (const float*)d_in[6];
    const float* w4 = (const float*)d_in[7];   const float* b4 = (const float*)d_in[8];
    const float* w5 = (const float*)d_in[9];   const float* b5 = (const float*)d_in[10];
    const float* w6 = (const float*)d_in[11];  const float* b6 = (const float*)d_in[12];
    const float* w7 = (const float*)d_in[13];  const float* b7 = (const float*)d_in[14];
    const float* dw1 = (const float*)d_in[15]; const float* db1 = (const float*)d_in[16];
    const float* dw2 = (const float*)d_in[17]; const float* db2 = (const float*)d_in[18];
    const float* dw3 = (const float*)d_in[19]; const float* db3 = (const float*)d_in[20];
    float* outp = (float*)d_out;

    void* p;
    cudaGetSymbolAddress(&p, g_op);  float* op = (float*)p;
    cudaGetSymbolAddress(&p, g_t1);  float* t1 = (float*)p;
    cudaGetSymbolAddress(&p, g_s1);  float* s1 = (float*)p;
    cudaGetSymbolAddress(&p, g_s2);  float* s2 = (float*)p;
    cudaGetSymbolAddress(&p, g_q1);  float* q1 = (float*)p;
    cudaGetSymbolAddress(&p, g_q2);  float* q2 = (float*)p;
    cudaGetSymbolAddress(&p, g_e1);  float* e1 = (float*)p;
    cudaGetSymbolAddress(&p, g_e2);  float* e2 = (float*)p;

    dim3 blk(32, 8);

    // 1) operator branches (pre-norm)
    op_kernel<<<dim3(W_ / 32, H_ / 8, B_ * C_), blk>>>(x);
    // 2) per-(sample,branch) mean/std
    stats1_kernel<<<20 * 64, 256>>>();
    stats2_kernel<<<20, 64>>>();
    // 3) conv1 (160 -> 32) with normalization folded into input load
    conv3x3_kernel<160, 1><<<dim3(16, 64, B_), blk>>>(op, w1, b1, t1, 512, 512, nullptr);
    // 4) pool -> conv2
    maxpool_kernel<<<(B_ * 32 * 256 * 256 + 255) / 256, 256>>>(t1, s1, 256, 256);
    conv3x3_kernel<32, 0><<<dim3(8, 32, B_), blk>>>(s1, w2, b2, s2, 256, 256, nullptr);
    // 5) pool -> conv3
    maxpool_kernel<<<(B_ * 32 * 128 * 128 + 255) / 256, 256>>>(s2, q1, 128, 128);
    conv3x3_kernel<32, 0><<<dim3(4, 16, B_), blk>>>(q1, w3, b3, q2, 128, 128, nullptr);
    // 6) pool -> conv4
    maxpool_kernel<<<(B_ * 32 * 64 * 64 + 255) / 256, 256>>>(q2, e1, 64, 64);
    conv3x3_kernel<32, 0><<<dim3(2, 8, B_), blk>>>(e1, w4, b4, e2, 64, 64, nullptr);
    // 7) deconv1 -> conv5
    deconv_kernel<<<dim3(2, 4, B_ * 64), blk>>>(e2, dw1, db1, q1, 64, 64);
    conv3x3_kernel<32, 0><<<dim3(4, 16, B_), blk>>>(q1, w5, b5, q2, 128, 128, nullptr);
    // 8) deconv2 -> conv6
    deconv_kernel<<<dim3(4, 4, B_ * 128), blk>>>(q2, dw2, db2, s1, 128, 128);
    conv3x3_kernel<32, 0><<<dim3(8, 32, B_), blk>>>(s1, w6, b6, s2, 256, 256, nullptr);
    // 9) deconv3 -> conv7 fused with orig * y
    deconv_kernel<<<dim3(8, 4, B_ * 256), blk>>>(s2, dw3, db3, t1, 256, 256);
    conv3x3_kernel<32, 2><<<dim3(16, 64, B_), blk>>>(t1, w7, b7, outp, 512, 512, x);
}

// round 2
// speedup vs baseline: 1.3824x; 1.3824x over previous
#include <cuda_runtime.h>

#define B_ 4
#define C_ 32
#define H_ 512
#define W_ 512

// ---------------- scratch (device globals; no runtime allocation) ----------------
static __device__ float g_t1[(size_t)B_ * C_ * H_ * W_];    // 512x512 feature map
static __device__ float g_s1[(size_t)B_ * C_ * 256 * 256];
static __device__ float g_s2[(size_t)B_ * C_ * 256 * 256];
static __device__ float g_q1[(size_t)B_ * C_ * 128 * 128];
static __device__ float g_q2[(size_t)B_ * C_ * 128 * 128];
static __device__ float g_e1[(size_t)B_ * C_ * 64 * 64];
static __device__ float g_e2[(size_t)B_ * C_ * 64 * 64];
static __device__ float g_partS[20 * 32768];
static __device__ float g_partQ[20 * 32768];
static __device__ float g_norm[40];                         // (mean, inv_std) per (b, branch)

// ---------------- shared edge-operator math ----------------
__device__ __forceinline__ void edge5(float a00, float a01, float a02,
                                      float a10, float a11, float a12,
                                      float a20, float a21, float a22, float o[5]) {
    // Sobel
    float sxv = -a00 + a02 - 2.f * a10 + 2.f * a12 - a20 + a22;
    float syv = -a00 - 2.f * a01 - a02 + a20 + 2.f * a21 + a22;
    o[0] = 0.5f * (sxv + syv);
    // Scharr
    float cxv = -3.f * a00 + 3.f * a02 - 10.f * a10 + 10.f * a12 - 3.f * a20 + 3.f * a22;
    float cyv = -3.f * a00 - 10.f * a01 - 3.f * a02 + 3.f * a20 + 10.f * a21 + 3.f * a22;
    o[1] = 0.5f * (cxv + cyv);
    // Laplace (cv2 ksize=3)
    o[2] = 2.f * a00 + 2.f * a02 - 8.f * a11 + 2.f * a20 + 2.f * a22;
    // Roberts, cv2 anchor: pad ((1,0),(1,0))
    o[3] = 0.5f * ((-a00 + a11) + (-a01 + a10));
    // Prewitt
    float pxv = a00 + a01 + a02 - a20 - a21 - a22;
    float pyv = -a00 + a02 - a10 + a12 - a20 + a22;
    o[4] = 0.5f * (pxv + pyv);
}

__device__ __forceinline__ int refl(int i, int n) {
    return i < 0 ? -i : (i >= n ? 2 * n - 2 - i : i);
}

// ---------------- fused operator + partial stats (reads x only) ----------------
// grid: (16, 64, B*C), block: (32, 8)
__global__ void stats_op_kernel(const float* __restrict__ x) {
    __shared__ float sx[10][34];
    __shared__ float red[8][10];
    const int tx = threadIdx.x, ty = threadIdx.y;
    const int tid = ty * 32 + tx;
    const int w0 = blockIdx.x * 32, h0 = blockIdx.y * 8;
    const int bc = blockIdx.z;
    const int b = bc >> 5, c = bc & 31;
    const float* xp = x + (size_t)bc * H_ * W_;

    for (int i = tid; i < 340; i += 256) {
        int r = i / 34, cl = i % 34;
        int hh = refl(h0 - 1 + r, H_);
        int ww = refl(w0 - 1 + cl, W_);
        sx[r][cl] = xp[hh * W_ + ww];
    }
    __syncthreads();

    float o[5];
    edge5(sx[ty + 0][tx + 0], sx[ty + 0][tx + 1], sx[ty + 0][tx + 2],
          sx[ty + 1][tx + 0], sx[ty + 1][tx + 1], sx[ty + 1][tx + 2],
          sx[ty + 2][tx + 0], sx[ty + 2][tx + 1], sx[ty + 2][tx + 2], o);

#pragma unroll
    for (int k = 0; k < 5; ++k) {
        float sv = o[k], qv = o[k] * o[k];
#pragma unroll
        for (int off = 16; off; off >>= 1) {
            sv += __shfl_down_sync(0xffffffffu, sv, off);
            qv += __shfl_down_sync(0xffffffffu, qv, off);
        }
        if (tx == 0) { red[ty][k] = sv; red[ty][5 + k] = qv; }
    }
    __syncthreads();
    if (tid < 10) {
        float t = 0.f;
#pragma unroll
        for (int w = 0; w < 8; ++w) t += red[w][tid];
        int tile = blockIdx.x + 16 * blockIdx.y + 1024 * c;
        if (tid < 5) g_partS[(b * 5 + tid) * 32768 + tile] = t;
        else         g_partQ[(b * 5 + tid - 5) * 32768 + tile] = t;
    }
}

// stage 2: grid 20 blocks, 256 threads
__global__ void stats2_kernel() {
    __shared__ float rs[256], rq[256];
    const int seg = blockIdx.x, t = threadIdx.x;
    float s = 0.f, q = 0.f;
    for (int i = t; i < 32768; i += 256) {
        s += g_partS[seg * 32768 + i];
        q += g_partQ[seg * 32768 + i];
    }
    rs[t] = s; rq[t] = q;
    __syncthreads();
    for (int st = 128; st > 0; st >>= 1) {
        if (t < st) { rs[t] += rs[t + st]; rq[t] += rq[t + st]; }
        __syncthreads();
    }
    if (t == 0) {
        const double N = (double)32 * H_ * W_;
        double mean = (double)rs[0] / N;
        double var = (double)rq[0] / N - mean * mean;
        if (var < 1e-30) var = 1e-30;
        g_norm[seg * 2 + 0] = (float)mean;
        g_norm[seg * 2 + 1] = (float)(1.0 / sqrt(var));
    }
}

// ---------------- conv1 fused: regenerate operator branches in-tile ----------------
// Output tile 32w x 16h, all 32 co. Thread: 16 co x 4 rows.
// grid: (16, 32, B), block: (32, 8)
__global__ void __launch_bounds__(256, 2)
conv1_fused_kernel(const float* __restrict__ x, const float* __restrict__ wgt,
                   const float* __restrict__ bias, float* __restrict__ out) {
    __shared__ float s_x[20 * 36];       // x tile with 2-halo (reflect)
    __shared__ float s_op[5 * 18 * 34];  // normalized operator tiles (zero outside image)
    __shared__ float s_w[5 * 288];       // [br][tap][co]
    __shared__ float s_nm[5], s_ns[5];

    const int tx = threadIdx.x, ty = threadIdx.y;
    const int tid = ty * 32 + tx;
    const int w0 = blockIdx.x * 32, h0 = blockIdx.y * 16;
    const int b = blockIdx.z;
    const int gr = ty & 3, ch = ty >> 2;

    if (tid < 5) {
        s_nm[tid] = g_norm[(b * 5 + tid) * 2 + 0];
        s_ns[tid] = g_norm[(b * 5 + tid) * 2 + 1];
    }

    float4 acc[4][4];
#pragma unroll
    for (int u = 0; u < 4; ++u) {
        float4 bv = make_float4(bias[ch * 16 + u * 4 + 0], bias[ch * 16 + u * 4 + 1],
                                bias[ch * 16 + u * 4 + 2], bias[ch * 16 + u * 4 + 3]);
#pragma unroll
        for (int p = 0; p < 4; ++p) acc[p][u] = bv;
    }

    for (int ci = 0; ci < 32; ++ci) {
        __syncthreads();
        // x tile (reflect-101)
        for (int i = tid; i < 720; i += 256) {
            int r = i / 36, cl = i % 36;
            int gh = refl(h0 - 2 + r, H_);
            int gw = refl(w0 - 2 + cl, W_);
            s_x[i] = x[(((size_t)b * 32 + ci) * H_ + gh) * W_ + gw];
        }
        // weights for this ci: all 5 branches
        for (int i = tid; i < 1440; i += 256) {
            int br = i / 288, rem = i - br * 288;
            int tap = rem >> 5, co = rem & 31;
            s_w[i] = wgt[((size_t)co * 160 + br * 32 + ci) * 9 + tap];
        }
        __syncthreads();
        // generate normalized operator tiles (conv1 zero-pad => 0 outside image)
        for (int i = tid; i < 612; i += 256) {
            int r = i / 34, cl = i % 34;
            int gh = h0 - 1 + r, gw = w0 - 1 + cl;
            float o[5] = {0.f, 0.f, 0.f, 0.f, 0.f};
            if (gh >= 0 && gh < H_ && gw >= 0 && gw < W_) {
                const float* p0 = &s_x[r * 36 + cl];
                edge5(p0[0], p0[1], p0[2], p0[36], p0[37], p0[38], p0[72], p0[73], p0[74], o);
#pragma unroll
                for (int k = 0; k < 5; ++k) o[k] = (o[k] - s_nm[k]) * s_ns[k];
            }
#pragma unroll
            for (int k = 0; k < 5; ++k) s_op[k * 612 + i] = o[k];
        }
        __syncthreads();
        // FMA over 5 branch-channels
#pragma unroll
        for (int br = 0; br < 5; ++br) {
            float vin[6][3];
#pragma unroll
            for (int k = 0; k < 6; ++k)
#pragma unroll
                for (int j = 0; j < 3; ++j)
                    vin[k][j] = s_op[br * 612 + (gr * 4 + k) * 34 + tx + j];
#pragma unroll
            for (int di = 0; di < 3; ++di)
#pragma unroll
                for (int dj = 0; dj < 3; ++dj) {
                    const float4* wp = (const float4*)(s_w + br * 288 + (di * 3 + dj) * 32) + ch * 4;
                    float4 q0 = wp[0], q1 = wp[1], q2 = wp[2], q3 = wp[3];
#pragma unroll
                    for (int p = 0; p < 4; ++p) {
                        float v = vin[p + di][dj];
                        acc[p][0].x += v * q0.x; acc[p][0].y += v * q0.y;
                        acc[p][0].z += v * q0.z; acc[p][0].w += v * q0.w;
                        acc[p][1].x += v * q1.x; acc[p][1].y += v * q1.y;
                        acc[p][1].z += v * q1.z; acc[p][1].w += v * q1.w;
                        acc[p][2].x += v * q2.x; acc[p][2].y += v * q2.y;
                        acc[p][2].z += v * q2.z; acc[p][2].w += v * q2.w;
                        acc[p][3].x += v * q3.x; acc[p][3].y += v * q3.y;
                        acc[p][3].z += v * q3.z; acc[p][3].w += v * q3.w;
                    }
                }
        }
    }

    const size_t plane = (size_t)H_ * W_;
#pragma unroll
    for (int p = 0; p < 4; ++p) {
        int h = h0 + gr * 4 + p;
        size_t ob = ((size_t)b * 32 + ch * 16) * plane + (size_t)h * W_ + (w0 + tx);
        const float* a = (const float*)acc[p];
#pragma unroll
        for (int j = 0; j < 16; ++j) out[ob + (size_t)j * plane] = a[j];
    }
}

// ---------------- conv3x3 CIN=32 (zero pad), register-blocked ----------------
// P pixels(rows) per thread, 16 co per thread; tile = 32w x (4P)h, 32 co.
// MODE 0: plain; MODE 2: fuse orig*y epilogue
// grid: (Ww/32, Hh/(4P), B), block: (32, 8)
template <int P, int MODE>
__global__ void __launch_bounds__(256, 2)
conv3x3_kernel(const float* __restrict__ in, const float* __restrict__ wgt,
               const float* __restrict__ bias, float* __restrict__ out,
               int Hh, int Ww, const float* __restrict__ orig) {
    constexpr int TH = 4 * P;
    constexpr int INR = TH + 2;
    __shared__ float s_in[4 * INR * 34];
    __shared__ float s_w[32 * 288];      // all weights [ci][tap][co]

    const int tx = threadIdx.x, ty = threadIdx.y;
    const int tid = ty * 32 + tx;
    const int w0 = blockIdx.x * 32, h0 = blockIdx.y * TH;
    const int b = blockIdx.z;
    const int gr = ty & 3, ch = ty >> 2;

    // preload all weights once
    for (int i = tid; i < 32 * 288; i += 256) {
        int ci = i / 288, rem = i - ci * 288;
        int tap = rem >> 5, co = rem & 31;
        s_w[i] = wgt[((size_t)co * 32 + ci) * 9 + tap];
    }

    float4 acc[P][4];
#pragma unroll
    for (int u = 0; u < 4; ++u) {
        float4 bv = make_float4(bias[ch * 16 + u * 4 + 0], bias[ch * 16 + u * 4 + 1],
                                bias[ch * 16 + u * 4 + 2], bias[ch * 16 + u * 4 + 3]);
#pragma unroll
        for (int p = 0; p < P; ++p) acc[p][u] = bv;
    }

    for (int ci0 = 0; ci0 < 32; ci0 += 4) {
        __syncthreads();
        for (int i = tid; i < 4 * INR * 34; i += 256) {
            int cc = i / (INR * 34), rem = i - cc * (INR * 34);
            int r = rem / 34, cl = rem - r * 34;
            int gh = h0 - 1 + r, gw = w0 - 1 + cl;
            float v = 0.f;
            if (gh >= 0 && gh < Hh && gw >= 0 && gw < Ww)
                v = in[(((size_t)b * 32 + ci0 + cc) * Hh + gh) * Ww + gw];
            s_in[i] = v;
        }
        __syncthreads();

#pragma unroll
        for (int cc = 0; cc < 4; ++cc) {
            float vin[P + 2][3];
#pragma unroll
            for (int k = 0; k < P + 2; ++k)
#pragma unroll
                for (int j = 0; j < 3; ++j)
                    vin[k][j] = s_in[cc * (INR * 34) + (gr * P + k) * 34 + tx + j];
            const float* wb = s_w + (ci0 + cc) * 288;
#pragma unroll
            for (int di = 0; di < 3; ++di)
#pragma unroll
                for (int dj = 0; dj < 3; ++dj) {
                    const float4* wp = (const float4*)(wb + (di * 3 + dj) * 32) + ch * 4;
                    float4 q0 = wp[0], q1 = wp[1], q2 = wp[2], q3 = wp[3];
#pragma unroll
                    for (int p = 0; p < P; ++p) {
                        float v = vin[p + di][dj];
                        acc[p][0].x += v * q0.x; acc[p][0].y += v * q0.y;
                        acc[p][0].z += v * q0.z; acc[p][0].w += v * q0.w;
                        acc[p][1].x += v * q1.x; acc[p][1].y += v * q1.y;
                        acc[p][1].z += v * q1.z; acc[p][1].w += v * q1.w;
                        acc[p][2].x += v * q2.x; acc[p][2].y += v * q2.y;
                        acc[p][2].z += v * q2.z; acc[p][2].w += v * q2.w;
                        acc[p][3].x += v * q3.x; acc[p][3].y += v * q3.y;
                        acc[p][3].z += v * q3.z; acc[p][3].w += v * q3.w;
                    }
                }
        }
    }

    const size_t plane = (size_t)Hh * Ww;
#pragma unroll
    for (int p = 0; p < P; ++p) {
        int h = h0 + gr * P + p;
        size_t ob = ((size_t)b * 32 + ch * 16) * plane + (size_t)h * Ww + (w0 + tx);
        const float* a = (const float*)acc[p];
#pragma unroll
        for (int j = 0; j < 16; ++j) {
            float r = a[j];
            if (MODE == 2) r *= orig[ob + (size_t)j * plane];
            out[ob + (size_t)j * plane] = r;
        }
    }
}

// ---------------- 2x2 max pool (Hh, Ww = OUTPUT dims) ----------------
__global__ void maxpool_kernel(const float* __restrict__ in, float* __restrict__ out,
                               int Hh, int Ww) {
    size_t n = (size_t)blockIdx.x * 256 + threadIdx.x;
    size_t total = (size_t)B_ * 32 * Hh * Ww;
    if (n >= total) return;
    int w = (int)(n % Ww);
    size_t r = n / Ww;
    int h = (int)(r % Hh);
    size_t bc = r / Hh;
    const float* p = in + (bc * (2 * (size_t)Hh) + 2 * h) * (2 * (size_t)Ww) + 2 * w;
    float m = fmaxf(fmaxf(p[0], p[1]), fmaxf(p[2 * Ww], p[2 * Ww + 1]));
    out[n] = m;
}

// ---------------- deconv 2x2 stride 2 ----------------
// grid: (Wi/32, 4, B*Hi), block: (32, 8)
__global__ void deconv_kernel(const float* __restrict__ in, const float* __restrict__ wgt,
                              const float* __restrict__ bias, float* __restrict__ out,
                              int Hi, int Wi) {
    __shared__ float sx[32][33];
    __shared__ float sw[32][8][4];
    const int tx = threadIdx.x, ty = threadIdx.y;
    const int tid = ty * 32 + tx;
    const int w0 = blockIdx.x * 32;
    const int oc0 = blockIdx.y * 8;
    const int bh = blockIdx.z;
    const int b = bh / Hi, h = bh % Hi;

    for (int i = tid; i < 1024; i += 256) {
        int ci = i >> 5, w = i & 31;
        sx[ci][w] = in[(((size_t)b * 32 + ci) * Hi + h) * Wi + (w0 + w)];
    }
    for (int i = tid; i < 1024; i += 256) {
        int ci = i >> 5, rem = i & 31;
        int ol = rem >> 2, pq = rem & 3;
        sw[ci][ol][pq] = wgt[(size_t)ci * 128 + (oc0 + ol) * 4 + pq];
    }
    __syncthreads();

    const int o = oc0 + ty;
    const float bv = bias[o];
    float a0 = bv, a1 = bv, a2 = bv, a3 = bv;
#pragma unroll
    for (int ci = 0; ci < 32; ++ci) {
        float v = sx[ci][tx];
        a0 += v * sw[ci][ty][0];
        a1 += v * sw[ci][ty][1];
        a2 += v * sw[ci][ty][2];
        a3 += v * sw[ci][ty][3];
    }
    const int Ho = 2 * Hi, Wo = 2 * Wi;
    size_t ob = (((size_t)b * 32 + o) * Ho + 2 * h) * (size_t)Wo + 2 * (w0 + tx);
    *(float2*)(out + ob) = make_float2(a0, a1);
    *(float2*)(out + ob + Wo) = make_float2(a2, a3);
}

// ---------------- host launch ----------------
extern "C" void kernel_launch(void* const* d_in, const int* in_sizes, int n_in,
                              void* d_out, int out_size) {
    const float* x = (const float*)d_in[0];
    const float* w1 = (const float*)d_in[1];   const float* b1 = (const float*)d_in[2];
    const float* w2 = (const float*)d_in[3];   const float* b2 = (const float*)d_in[4];
    const float* w3 = (const float*)d_in[5];   const float* b3 = (const float*)d_in[6];
    const float* w4 = (const float*)d_in[7];   const float* b4 = (const float*)d_in[8];
    const float* w5 = (const float*)d_in[9];   const float* b5 = (const float*)d_in[10];
    const float* w6 = (const float*)d_in[11];  const float* b6 = (const float*)d_in[12];
    const float* w7 = (const float*)d_in[13];  const float* b7 = (const float*)d_in[14];
    const float* dw1 = (const float*)d_in[15]; const float* db1 = (const float*)d_in[16];
    const float* dw2 = (const float*)d_in[17]; const float* db2 = (const float*)d_in[18];
    const float* dw3 = (const float*)d_in[19]; const float* db3 = (const float*)d_in[20];
    float* outp = (float*)d_out;

    void* p;
    cudaGetSymbolAddress(&p, g_t1);  float* t1 = (float*)p;
    cudaGetSymbolAddress(&p, g_s1);  float* s1 = (float*)p;
    cudaGetSymbolAddress(&p, g_s2);  float* s2 = (float*)p;
    cudaGetSymbolAddress(&p, g_q1);  float* q1 = (float*)p;
    cudaGetSymbolAddress(&p, g_q2);  float* q2 = (float*)p;
    cudaGetSymbolAddress(&p, g_e1);  float* e1 = (float*)p;
    cudaGetSymbolAddress(&p, g_e2);  float* e2 = (float*)p;

    dim3 blk(32, 8);

    // stats (fused operator recompute, deterministic two-stage)
    stats_op_kernel<<<dim3(16, 64, B_ * C_), blk>>>(x);
    stats2_kernel<<<20, 256>>>();

    // conv1 fused (operator regen + norm + 3x3 conv, 160 -> 32)
    conv1_fused_kernel<<<dim3(16, 32, B_), blk>>>(x, w1, b1, t1);

    // pool -> conv2 (256^2)
    maxpool_kernel<<<(B_ * 32 * 256 * 256 + 255) / 256, 256>>>(t1, s1, 256, 256);
    conv3x3_kernel<4, 0><<<dim3(8, 16, B_), blk>>>(s1, w2, b2, s2, 256, 256, nullptr);
    // pool -> conv3 (128^2)
    maxpool_kernel<<<(B_ * 32 * 128 * 128 + 255) / 256, 256>>>(s2, q1, 128, 128);
    conv3x3_kernel<2, 0><<<dim3(4, 16, B_), blk>>>(q1, w3, b3, q2, 128, 128, nullptr);
    // pool -> conv4 (64^2)
    maxpool_kernel<<<(B_ * 32 * 64 * 64 + 255) / 256, 256>>>(q2, e1, 64, 64);
    conv3x3_kernel<1, 0><<<dim3(2, 16, B_), blk>>>(e1, w4, b4, e2, 64, 64, nullptr);
    // deconv1 -> conv5 (128^2)
    deconv_kernel<<<dim3(2, 4, B_ * 64), blk>>>(e2, dw1, db1, q1, 64, 64);
    conv3x3_kernel<2, 0><<<dim3(4, 16, B_), blk>>>(q1, w5, b5, q2, 128, 128, nullptr);
    // deconv2 -> conv6 (256^2)
    deconv_kernel<<<dim3(4, 4, B_ * 128), blk>>>(q2, dw2, db2, s1, 128, 128);
    conv3x3_kernel<4, 0><<<dim3(8, 16, B_), blk>>>(s1, w6, b6, s2, 256, 256, nullptr);
    // deconv3 -> conv7 (512^2) fused with orig * y
    deconv_kernel<<<dim3(8, 4, B_ * 256), blk>>>(s2, dw3, db3, t1, 256, 256);
    conv3x3_kernel<4, 2><<<dim3(16, 32, B_), blk>>>(t1, w7, b7, outp, 512, 512, x);
}

// round 3
// speedup vs baseline: 1.5374x; 1.1122x over previous
#include <cuda_runtime.h>

#define B_ 4
#define C_ 32
#define H_ 512
#define W_ 512

// ---------------- scratch (device globals; no runtime allocation) ----------------
static __device__ float g_t1[(size_t)B_ * C_ * H_ * W_];    // 512x512 feature map
static __device__ float g_s1[(size_t)B_ * C_ * 256 * 256];
static __device__ float g_s2[(size_t)B_ * C_ * 256 * 256];
static __device__ float g_q1[(size_t)B_ * C_ * 128 * 128];
static __device__ float g_q2[(size_t)B_ * C_ * 128 * 128];
static __device__ float g_e1[(size_t)B_ * C_ * 64 * 64];
static __device__ float g_e2[(size_t)B_ * C_ * 64 * 64];
static __device__ float g_partS[20 * 32768];
static __device__ float g_partQ[20 * 32768];
static __device__ float g_norm[40];                         // (mean, inv_std) per (b, branch)

// ---------------- packed f32x2 helpers ----------------
typedef unsigned long long u64;

__device__ __forceinline__ u64 pk(float v) {                 // {v, v}
    u64 r; asm("mov.b64 %0, {%1, %1};" : "=l"(r) : "f"(v)); return r;
}
__device__ __forceinline__ u64 pk2(float a, float b) {       // {a, b}
    u64 r; asm("mov.b64 %0, {%1, %2};" : "=l"(r) : "f"(a), "f"(b)); return r;
}
__device__ __forceinline__ void fma2(u64& d, u64 a, u64 b) { // d += a*b (packed)
    asm("fma.rn.f32x2 %0, %1, %2, %0;" : "+l"(d) : "l"(a), "l"(b));
}
__device__ __forceinline__ void unpk(u64 v, float& lo, float& hi) {
    asm("mov.b64 {%0, %1}, %2;" : "=f"(lo), "=f"(hi) : "l"(v));
}

// ---------------- shared edge-operator math ----------------
__device__ __forceinline__ void edge5(float a00, float a01, float a02,
                                      float a10, float a11, float a12,
                                      float a20, float a21, float a22, float o[5]) {
    float sxv = -a00 + a02 - 2.f * a10 + 2.f * a12 - a20 + a22;
    float syv = -a00 - 2.f * a01 - a02 + a20 + 2.f * a21 + a22;
    o[0] = 0.5f * (sxv + syv);
    float cxv = -3.f * a00 + 3.f * a02 - 10.f * a10 + 10.f * a12 - 3.f * a20 + 3.f * a22;
    float cyv = -3.f * a00 - 10.f * a01 - 3.f * a02 + 3.f * a20 + 10.f * a21 + 3.f * a22;
    o[1] = 0.5f * (cxv + cyv);
    o[2] = 2.f * a00 + 2.f * a02 - 8.f * a11 + 2.f * a20 + 2.f * a22;
    o[3] = 0.5f * ((-a00 + a11) + (-a01 + a10));
    float pxv = a00 + a01 + a02 - a20 - a21 - a22;
    float pyv = -a00 + a02 - a10 + a12 - a20 + a22;
    o[4] = 0.5f * (pxv + pyv);
}

__device__ __forceinline__ int refl(int i, int n) {
    return i < 0 ? -i : (i >= n ? 2 * n - 2 - i : i);
}

// ---------------- fused operator + partial stats (reads x only) ----------------
// grid: (16, 64, B*C), block: (32, 8)
__global__ void stats_op_kernel(const float* __restrict__ x) {
    __shared__ float sx[10][34];
    __shared__ float red[8][10];
    const int tx = threadIdx.x, ty = threadIdx.y;
    const int tid = ty * 32 + tx;
    const int w0 = blockIdx.x * 32, h0 = blockIdx.y * 8;
    const int bc = blockIdx.z;
    const int b = bc >> 5, c = bc & 31;
    const float* xp = x + (size_t)bc * H_ * W_;

    for (int i = tid; i < 340; i += 256) {
        int r = i / 34, cl = i % 34;
        sx[r][cl] = xp[refl(h0 - 1 + r, H_) * W_ + refl(w0 - 1 + cl, W_)];
    }
    __syncthreads();

    float o[5];
    edge5(sx[ty + 0][tx + 0], sx[ty + 0][tx + 1], sx[ty + 0][tx + 2],
          sx[ty + 1][tx + 0], sx[ty + 1][tx + 1], sx[ty + 1][tx + 2],
          sx[ty + 2][tx + 0], sx[ty + 2][tx + 1], sx[ty + 2][tx + 2], o);

#pragma unroll
    for (int k = 0; k < 5; ++k) {
        float sv = o[k], qv = o[k] * o[k];
#pragma unroll
        for (int off = 16; off; off >>= 1) {
            sv += __shfl_down_sync(0xffffffffu, sv, off);
            qv += __shfl_down_sync(0xffffffffu, qv, off);
        }
        if (tx == 0) { red[ty][k] = sv; red[ty][5 + k] = qv; }
    }
    __syncthreads();
    if (tid < 10) {
        float t = 0.f;
#pragma unroll
        for (int w = 0; w < 8; ++w) t += red[w][tid];
        int tile = blockIdx.x + 16 * blockIdx.y + 1024 * c;
        if (tid < 5) g_partS[(b * 5 + tid) * 32768 + tile] = t;
        else         g_partQ[(b * 5 + tid - 5) * 32768 + tile] = t;
    }
}

// stage 2: grid 20 blocks, 256 threads
__global__ void stats2_kernel() {
    __shared__ float rs[256], rq[256];
    const int seg = blockIdx.x, t = threadIdx.x;
    float s = 0.f, q = 0.f;
    for (int i = t; i < 32768; i += 256) {
        s += g_partS[seg * 32768 + i];
        q += g_partQ[seg * 32768 + i];
    }
    rs[t] = s; rq[t] = q;
    __syncthreads();
    for (int st = 128; st > 0; st >>= 1) {
        if (t < st) { rs[t] += rs[t + st]; rq[t] += rq[t + st]; }
        __syncthreads();
    }
    if (t == 0) {
        const double N = (double)32 * H_ * W_;
        double mean = (double)rs[0] / N;
        double var = (double)rq[0] / N - mean * mean;
        if (var < 1e-30) var = 1e-30;
        g_norm[seg * 2 + 0] = (float)mean;
        g_norm[seg * 2 + 1] = (float)(1.0 / sqrt(var));
    }
}

// ---------------- conv1 fused: regenerate operator branches in-tile, f32x2 FMA ----------------
// Output tile 32w x 16h, all 32 co. Thread: 16 co (8 pairs) x 4 rows.
// grid: (16, 32, B), block: (32, 8)
__global__ void __launch_bounds__(256, 2)
conv1_fused_kernel(const float* __restrict__ x, const float* __restrict__ wgt,
                   const float* __restrict__ bias, float* __restrict__ out) {
    __shared__ __align__(16) float s_x[20 * 36];       // x tile, 2-halo (reflect)
    __shared__ __align__(16) float s_op[5 * 18 * 34];  // normalized operator tiles
    __shared__ __align__(16) float s_w[5 * 288];       // [br][tap][co]
    __shared__ float s_nm[5], s_ns[5];

    const int tx = threadIdx.x, ty = threadIdx.y;
    const int tid = ty * 32 + tx;
    const int w0 = blockIdx.x * 32, h0 = blockIdx.y * 16;
    const int b = blockIdx.z;
    const int gr = ty & 3, ch = ty >> 2;

    if (tid < 5) {
        s_nm[tid] = g_norm[(b * 5 + tid) * 2 + 0];
        s_ns[tid] = g_norm[(b * 5 + tid) * 2 + 1];
    }

    u64 acc[4][8];
#pragma unroll
    for (int j = 0; j < 8; ++j) {
        u64 bv = pk2(bias[ch * 16 + 2 * j], bias[ch * 16 + 2 * j + 1]);
#pragma unroll
        for (int p = 0; p < 4; ++p) acc[p][j] = bv;
    }

    for (int ci = 0; ci < 32; ++ci) {
        __syncthreads();
        for (int i = tid; i < 720; i += 256) {
            int r = i / 36, cl = i % 36;
            s_x[i] = x[(((size_t)b * 32 + ci) * H_ + refl(h0 - 2 + r, H_)) * W_ + refl(w0 - 2 + cl, W_)];
        }
        for (int i = tid; i < 1440; i += 256) {
            int br = i / 288, rem = i - br * 288;
            int tap = rem >> 5, co = rem & 31;
            s_w[i] = wgt[((size_t)co * 160 + br * 32 + ci) * 9 + tap];
        }
        __syncthreads();
        for (int i = tid; i < 612; i += 256) {
            int r = i / 34, cl = i % 34;
            int gh = h0 - 1 + r, gw = w0 - 1 + cl;
            float o[5] = {0.f, 0.f, 0.f, 0.f, 0.f};
            if (gh >= 0 && gh < H_ && gw >= 0 && gw < W_) {
                const float* p0 = &s_x[r * 36 + cl];
                edge5(p0[0], p0[1], p0[2], p0[36], p0[37], p0[38], p0[72], p0[73], p0[74], o);
#pragma unroll
                for (int k = 0; k < 5; ++k) o[k] = (o[k] - s_nm[k]) * s_ns[k];
            }
#pragma unroll
            for (int k = 0; k < 5; ++k) s_op[k * 612 + i] = o[k];
        }
        __syncthreads();

#pragma unroll
        for (int br = 0; br < 5; ++br) {
            const float* ib = s_op + br * 612 + (gr * 4) * 34 + tx;
            const float* wb = s_w + br * 288;
#pragma unroll
            for (int di = 0; di < 3; ++di) {
                u64 vp[4][3];
#pragma unroll
                for (int p = 0; p < 4; ++p)
#pragma unroll
                    for (int dj = 0; dj < 3; ++dj)
                        vp[p][dj] = pk(ib[(p + di) * 34 + dj]);
#pragma unroll
                for (int dj = 0; dj < 3; ++dj) {
                    const u64* wp = (const u64*)(wb + (di * 3 + dj) * 32) + ch * 8;
                    u64 q0 = wp[0], q1 = wp[1], q2 = wp[2], q3 = wp[3];
                    u64 q4 = wp[4], q5 = wp[5], q6 = wp[6], q7 = wp[7];
#pragma unroll
                    for (int p = 0; p < 4; ++p) {
                        u64 v = vp[p][dj];
                        fma2(acc[p][0], v, q0); fma2(acc[p][1], v, q1);
                        fma2(acc[p][2], v, q2); fma2(acc[p][3], v, q3);
                        fma2(acc[p][4], v, q4); fma2(acc[p][5], v, q5);
                        fma2(acc[p][6], v, q6); fma2(acc[p][7], v, q7);
                    }
                }
            }
        }
    }

    const size_t plane = (size_t)H_ * W_;
#pragma unroll
    for (int p = 0; p < 4; ++p) {
        int h = h0 + gr * 4 + p;
        size_t ob = ((size_t)b * 32 + ch * 16) * plane + (size_t)h * W_ + (w0 + tx);
#pragma unroll
        for (int j = 0; j < 8; ++j) {
            float lo, hi;
            unpk(acc[p][j], lo, hi);
            out[ob + (size_t)(2 * j) * plane] = lo;
            out[ob + (size_t)(2 * j + 1) * plane] = hi;
        }
    }
}

// ---------------- conv3x3 CIN=32 (zero pad), f32x2 register-blocked ----------------
// P pixels(rows) per thread, 16 co (8 pairs); tile = 32w x (4P)h, 32 co.
// MODE 0: plain; MODE 2: fuse orig*y epilogue
// grid: (Ww/32, Hh/(4P), B), block: (32, 8)
template <int P, int MODE>
__global__ void __launch_bounds__(256, 2)
conv3x3_kernel(const float* __restrict__ in, const float* __restrict__ wgt,
               const float* __restrict__ bias, float* __restrict__ out,
               int Hh, int Ww, const float* __restrict__ orig) {
    constexpr int TH = 4 * P;
    constexpr int INR = TH + 2;
    __shared__ __align__(16) float s_in[4 * INR * 34];
    __shared__ __align__(16) float s_w[32 * 288];      // all weights [ci][tap][co]

    const int tx = threadIdx.x, ty = threadIdx.y;
    const int tid = ty * 32 + tx;
    const int w0 = blockIdx.x * 32, h0 = blockIdx.y * TH;
    const int b = blockIdx.z;
    const int gr = ty & 3, ch = ty >> 2;

    for (int i = tid; i < 32 * 288; i += 256) {
        int ci = i / 288, rem = i - ci * 288;
        int tap = rem >> 5, co = rem & 31;
        s_w[i] = wgt[((size_t)co * 32 + ci) * 9 + tap];
    }

    u64 acc[P][8];
#pragma unroll
    for (int j = 0; j < 8; ++j) {
        u64 bv = pk2(bias[ch * 16 + 2 * j], bias[ch * 16 + 2 * j + 1]);
#pragma unroll
        for (int p = 0; p < P; ++p) acc[p][j] = bv;
    }

    for (int ci0 = 0; ci0 < 32; ci0 += 4) {
        __syncthreads();
        for (int i = tid; i < 4 * INR * 34; i += 256) {
            int cc = i / (INR * 34), rem = i - cc * (INR * 34);
            int r = rem / 34, cl = rem - r * 34;
            int gh = h0 - 1 + r, gw = w0 - 1 + cl;
            float v = 0.f;
            if (gh >= 0 && gh < Hh && gw >= 0 && gw < Ww)
                v = in[(((size_t)b * 32 + ci0 + cc) * Hh + gh) * Ww + gw];
            s_in[i] = v;
        }
        __syncthreads();

#pragma unroll
        for (int cc = 0; cc < 4; ++cc) {
            const float* ib = s_in + cc * (INR * 34) + (gr * P) * 34 + tx;
            const float* wb = s_w + (ci0 + cc) * 288;
#pragma unroll
            for (int di = 0; di < 3; ++di) {
                u64 vp[P][3];
#pragma unroll
                for (int p = 0; p < P; ++p)
#pragma unroll
                    for (int dj = 0; dj < 3; ++dj)
                        vp[p][dj] = pk(ib[(p + di) * 34 + dj]);
#pragma unroll
                for (int dj = 0; dj < 3; ++dj) {
                    const u64* wp = (const u64*)(wb + (di * 3 + dj) * 32) + ch * 8;
                    u64 q0 = wp[0], q1 = wp[1], q2 = wp[2], q3 = wp[3];
                    u64 q4 = wp[4], q5 = wp[5], q6 = wp[6], q7 = wp[7];
#pragma unroll
                    for (int p = 0; p < P; ++p) {
                        u64 v = vp[p][dj];
                        fma2(acc[p][0], v, q0); fma2(acc[p][1], v, q1);
                        fma2(acc[p][2], v, q2); fma2(acc[p][3], v, q3);
                        fma2(acc[p][4], v, q4); fma2(acc[p][5], v, q5);
                        fma2(acc[p][6], v, q6); fma2(acc[p][7], v, q7);
                    }
                }
            }
        }
    }

    const size_t plane = (size_t)Hh * Ww;
#pragma unroll
    for (int p = 0; p < P; ++p) {
        int h = h0 + gr * P + p;
        size_t ob = ((size_t)b * 32 + ch * 16) * plane + (size_t)h * Ww + (w0 + tx);
#pragma unroll
        for (int j = 0; j < 8; ++j) {
            float lo, hi;
            unpk(acc[p][j], lo, hi);
            if (MODE == 2) {
                lo *= orig[ob + (size_t)(2 * j) * plane];
                hi *= orig[ob + (size_t)(2 * j + 1) * plane];
            }
            out[ob + (size_t)(2 * j) * plane] = lo;
            out[ob + (size_t)(2 * j + 1) * plane] = hi;
        }
    }
}

// ---------------- 2x2 max pool (Hh, Ww = OUTPUT dims) ----------------
__global__ void maxpool_kernel(const float* __restrict__ in, float* __restrict__ out,
                               int Hh, int Ww) {
    size_t n = (size_t)blockIdx.x * 256 + threadIdx.x;
    size_t total = (size_t)B_ * 32 * Hh * Ww;
    if (n >= total) return;
    int w = (int)(n % Ww);
    size_t r = n / Ww;
    int h = (int)(r % Hh);
    size_t bc = r / Hh;
    const float* p = in + (bc * (2 * (size_t)Hh) + 2 * h) * (2 * (size_t)Ww) + 2 * w;
    float m = fmaxf(fmaxf(p[0], p[1]), fmaxf(p[2 * Ww], p[2 * Ww + 1]));
    out[n] = m;
}

// ---------------- deconv 2x2 stride 2 ----------------
// grid: (Wi/32, 4, B*Hi), block: (32, 8)
__global__ void deconv_kernel(const float* __restrict__ in, const float* __restrict__ wgt,
                              const float* __restrict__ bias, float* __restrict__ out,
                              int Hi, int Wi) {
    __shared__ float sx[32][33];
    __shared__ __align__(16) float sw[32][8][4];
    const int tx = threadIdx.x, ty = threadIdx.y;
    const int tid = ty * 32 + tx;
    const int w0 = blockIdx.x * 32;
    const int oc0 = blockIdx.y * 8;
    const int bh = blockIdx.z;
    const int b = bh / Hi, h = bh % Hi;

    for (int i = tid; i < 1024; i += 256) {
        int ci = i >> 5, w = i & 31;
        sx[ci][w] = in[(((size_t)b * 32 + ci) * Hi + h) * Wi + (w0 + w)];
    }
    for (int i = tid; i < 1024; i += 256) {
        int ci = i >> 5, rem = i & 31;
        int ol = rem >> 2, pq = rem & 3;
        sw[ci][ol][pq] = wgt[(size_t)ci * 128 + (oc0 + ol) * 4 + pq];
    }
    __syncthreads();

    const int o = oc0 + ty;
    const float bv = bias[o];
    u64 a01 = pk2(bv, bv), a23 = pk2(bv, bv);
#pragma unroll
    for (int ci = 0; ci < 32; ++ci) {
        u64 v = pk(sx[ci][tx]);
        const u64* wq = (const u64*)&sw[ci][ty][0];
        fma2(a01, v, wq[0]);
        fma2(a23, v, wq[1]);
    }
    float a0, a1, a2, a3;
    unpk(a01, a0, a1); unpk(a23, a2, a3);
    const int Ho = 2 * Hi, Wo = 2 * Wi;
    size_t ob = (((size_t)b * 32 + o) * Ho + 2 * h) * (size_t)Wo + 2 * (w0 + tx);
    *(float2*)(out + ob) = make_float2(a0, a1);
    *(float2*)(out + ob + Wo) = make_float2(a2, a3);
}

// ---------------- host launch ----------------
extern "C" void kernel_launch(void* const* d_in, const int* in_sizes, int n_in,
                              void* d_out, int out_size) {
    const float* x = (const float*)d_in[0];
    const float* w1 = (const float*)d_in[1];   const float* b1 = (const float*)d_in[2];
    const float* w2 = (const float*)d_in[3];   const float* b2 = (const float*)d_in[4];
    const float* w3 = (const float*)d_in[5];   const float* b3 = (const float*)d_in[6];
    const float* w4 = (const float*)d_in[7];   const float* b4 = (const float*)d_in[8];
    const float* w5 = (const float*)d_in[9];   const float* b5 = (const float*)d_in[10];
    const float* w6 = (const float*)d_in[11];  const float* b6 = (const float*)d_in[12];
    const float* w7 = (const float*)d_in[13];  const float* b7 = (const float*)d_in[14];
    const float* dw1 = (const float*)d_in[15]; const float* db1 = (const float*)d_in[16];
    const float* dw2 = (const float*)d_in[17]; const float* db2 = (const float*)d_in[18];
    const float* dw3 = (const float*)d_in[19]; const float* db3 = (const float*)d_in[20];
    float* outp = (float*)d_out;

    void* p;
    cudaGetSymbolAddress(&p, g_t1);  float* t1 = (float*)p;
    cudaGetSymbolAddress(&p, g_s1);  float* s1 = (float*)p;
    cudaGetSymbolAddress(&p, g_s2);  float* s2 = (float*)p;
    cudaGetSymbolAddress(&p, g_q1);  float* q1 = (float*)p;
    cudaGetSymbolAddress(&p, g_q2);  float* q2 = (float*)p;
    cudaGetSymbolAddress(&p, g_e1);  float* e1 = (float*)p;
    cudaGetSymbolAddress(&p, g_e2);  float* e2 = (float*)p;

    dim3 blk(32, 8);

    // stats (fused operator recompute, deterministic two-stage)
    stats_op_kernel<<<dim3(16, 64, B_ * C_), blk>>>(x);
    stats2_kernel<<<20, 256>>>();

    // conv1 fused (operator regen + norm + 3x3 conv, 160 -> 32)
    conv1_fused_kernel<<<dim3(16, 32, B_), blk>>>(x, w1, b1, t1);

    // pool -> conv2 (256^2)
    maxpool_kernel<<<(B_ * 32 * 256 * 256 + 255) / 256, 256>>>(t1, s1, 256, 256);
    conv3x3_kernel<4, 0><<<dim3(8, 16, B_), blk>>>(s1, w2, b2, s2, 256, 256, nullptr);
    // pool -> conv3 (128^2)
    maxpool_kernel<<<(B_ * 32 * 128 * 128 + 255) / 256, 256>>>(s2, q1, 128, 128);
    conv3x3_kernel<2, 0><<<dim3(4, 16, B_), blk>>>(q1, w3, b3, q2, 128, 128, nullptr);
    // pool -> conv4 (64^2)
    maxpool_kernel<<<(B_ * 32 * 64 * 64 + 255) / 256, 256>>>(q2, e1, 64, 64);
    conv3x3_kernel<1, 0><<<dim3(2, 16, B_), blk>>>(e1, w4, b4, e2, 64, 64, nullptr);
    // deconv1 -> conv5 (128^2)
    deconv_kernel<<<dim3(2, 4, B_ * 64), blk>>>(e2, dw1, db1, q1, 64, 64);
    conv3x3_kernel<2, 0><<<dim3(4, 16, B_), blk>>>(q1, w5, b5, q2, 128, 128, nullptr);
    // deconv2 -> conv6 (256^2)
    deconv_kernel<<<dim3(4, 4, B_ * 128), blk>>>(q2, dw2, db2, s1, 128, 128);
    conv3x3_kernel<4, 0><<<dim3(8, 16, B_), blk>>>(s1, w6, b6, s2, 256, 256, nullptr);
    // deconv3 -> conv7 (512^2) fused with orig * y
    deconv_kernel<<<dim3(8, 4, B_ * 256), blk>>>(s2, dw3, db3, t1, 256, 256);
    conv3x3_kernel<4, 2><<<dim3(16, 32, B_), blk>>>(t1, w7, b7, outp, 512, 512, x);
}

// round 4
// speedup vs baseline: 1.7032x; 1.1078x over previous
#include <cuda_runtime.h>

#define B_ 4
#define C_ 32
#define H_ 512
#define W_ 512

// ---------------- scratch (device globals; no runtime allocation) ----------------
static __device__ float g_t1[(size_t)B_ * C_ * H_ * W_];    // 512x512
static __device__ float g_s1[(size_t)B_ * C_ * 256 * 256];
static __device__ float g_s2[(size_t)B_ * C_ * 256 * 256];
static __device__ float g_q1[(size_t)B_ * C_ * 128 * 128];
static __device__ float g_q2[(size_t)B_ * C_ * 128 * 128];
static __device__ float g_e1[(size_t)B_ * C_ * 64 * 64];
static __device__ float g_e2[(size_t)B_ * C_ * 64 * 64];
static __device__ float g_partS[20 * 32768];
static __device__ float g_partQ[20 * 32768];
static __device__ float g_norm[40];                         // (mean, inv_std) per (b, branch)

// ---------------- packed f32x2 helpers ----------------
typedef unsigned long long u64;

__device__ __forceinline__ u64 pk(float v) {                 // {v, v}
    u64 r; asm("mov.b64 %0, {%1, %1};" : "=l"(r) : "f"(v)); return r;
}
__device__ __forceinline__ u64 pk2(float a, float b) {       // {a, b}
    u64 r; asm("mov.b64 %0, {%1, %2};" : "=l"(r) : "f"(a), "f"(b)); return r;
}
__device__ __forceinline__ void fma2(u64& d, u64 a, u64 b) { // d += a*b (packed)
    asm("fma.rn.f32x2 %0, %1, %2, %0;" : "+l"(d) : "l"(a), "l"(b));
}
__device__ __forceinline__ void unpk(u64 v, float& lo, float& hi) {
    asm("mov.b64 {%0, %1}, %2;" : "=f"(lo), "=f"(hi) : "l"(v));
}

// ---------------- shared edge-operator math ----------------
__device__ __forceinline__ void edge5(float a00, float a01, float a02,
                                      float a10, float a11, float a12,
                                      float a20, float a21, float a22, float o[5]) {
    float sxv = -a00 + a02 - 2.f * a10 + 2.f * a12 - a20 + a22;
    float syv = -a00 - 2.f * a01 - a02 + a20 + 2.f * a21 + a22;
    o[0] = 0.5f * (sxv + syv);
    float cxv = -3.f * a00 + 3.f * a02 - 10.f * a10 + 10.f * a12 - 3.f * a20 + 3.f * a22;
    float cyv = -3.f * a00 - 10.f * a01 - 3.f * a02 + 3.f * a20 + 10.f * a21 + 3.f * a22;
    o[1] = 0.5f * (cxv + cyv);
    o[2] = 2.f * a00 + 2.f * a02 - 8.f * a11 + 2.f * a20 + 2.f * a22;
    o[3] = 0.5f * ((-a00 + a11) + (-a01 + a10));
    float pxv = a00 + a01 + a02 - a20 - a21 - a22;
    float pyv = -a00 + a02 - a10 + a12 - a20 + a22;
    o[4] = 0.5f * (pxv + pyv);
}

__device__ __forceinline__ int refl(int i, int n) {
    return i < 0 ? -i : (i >= n ? 2 * n - 2 - i : i);
}

// ---------------- fused operator + partial stats (reads x only) ----------------
// grid: (16, 64, B*C), block: (32, 8)
__global__ void stats_op_kernel(const float* __restrict__ x) {
    __shared__ float sx[10][34];
    __shared__ float red[8][10];
    const int tx = threadIdx.x, ty = threadIdx.y;
    const int tid = ty * 32 + tx;
    const int w0 = blockIdx.x * 32, h0 = blockIdx.y * 8;
    const int bc = blockIdx.z;
    const int b = bc >> 5, c = bc & 31;
    const float* xp = x + (size_t)bc * H_ * W_;

    for (int i = tid; i < 340; i += 256) {
        int r = i / 34, cl = i % 34;
        sx[r][cl] = xp[refl(h0 - 1 + r, H_) * W_ + refl(w0 - 1 + cl, W_)];
    }
    __syncthreads();

    float o[5];
    edge5(sx[ty + 0][tx + 0], sx[ty + 0][tx + 1], sx[ty + 0][tx + 2],
          sx[ty + 1][tx + 0], sx[ty + 1][tx + 1], sx[ty + 1][tx + 2],
          sx[ty + 2][tx + 0], sx[ty + 2][tx + 1], sx[ty + 2][tx + 2], o);

#pragma unroll
    for (int k = 0; k < 5; ++k) {
        float sv = o[k], qv = o[k] * o[k];
#pragma unroll
        for (int off = 16; off; off >>= 1) {
            sv += __shfl_down_sync(0xffffffffu, sv, off);
            qv += __shfl_down_sync(0xffffffffu, qv, off);
        }
        if (tx == 0) { red[ty][k] = sv; red[ty][5 + k] = qv; }
    }
    __syncthreads();
    if (tid < 10) {
        float t = 0.f;
#pragma unroll
        for (int w = 0; w < 8; ++w) t += red[w][tid];
        int tile = blockIdx.x + 16 * blockIdx.y + 1024 * c;
        if (tid < 5) g_partS[(b * 5 + tid) * 32768 + tile] = t;
        else         g_partQ[(b * 5 + tid - 5) * 32768 + tile] = t;
    }
}

// stage 2: grid 20 blocks, 256 threads
__global__ void stats2_kernel() {
    __shared__ float rs[256], rq[256];
    const int seg = blockIdx.x, t = threadIdx.x;
    float s = 0.f, q = 0.f;
    for (int i = t; i < 32768; i += 256) {
        s += g_partS[seg * 32768 + i];
        q += g_partQ[seg * 32768 + i];
    }
    rs[t] = s; rq[t] = q;
    __syncthreads();
    for (int st = 128; st > 0; st >>= 1) {
        if (t < st) { rs[t] += rs[t + st]; rq[t] += rq[t + st]; }
        __syncthreads();
    }
    if (t == 0) {
        const double N = (double)32 * H_ * W_;
        double mean = (double)rs[0] / N;
        double var = (double)rq[0] / N - mean * mean;
        if (var < 1e-30) var = 1e-30;
        g_norm[seg * 2 + 0] = (float)mean;
        g_norm[seg * 2 + 1] = (float)(1.0 / sqrt(var));
    }
}

// ---------------- conv1 fused (op regen + norm + conv + POOL), pipelined ----------------
// Output tile 32w x 16h -> pooled 16w x 8h of 256^2. grid: (16, 32, B), block: (32, 8)
__global__ void __launch_bounds__(256, 2)
conv1_fused_kernel(const float* __restrict__ x, const float* __restrict__ wgt,
                   const float* __restrict__ bias, float* __restrict__ out) {
    __shared__ __align__(16) float s_x[2][720];         // 20x36 x-tile, 2-halo
    __shared__ __align__(16) float s_op[5 * 612];       // 18x34 normalized op tiles
    __shared__ __align__(16) float s_w[2][1440];        // [br][tap][co]
    __shared__ float s_nm[5], s_ns[5];

    const int tx = threadIdx.x, ty = threadIdx.y;
    const int tid = ty * 32 + tx;
    const int w0 = blockIdx.x * 32, h0 = blockIdx.y * 16;
    const int b = blockIdx.z;
    const int gr = ty & 3, ch = ty >> 2;

    if (tid < 5) {
        s_nm[tid] = g_norm[(b * 5 + tid) * 2 + 0];
        s_ns[tid] = g_norm[(b * 5 + tid) * 2 + 1];
    }

    // initial fill: ci = 0
    {
#pragma unroll
        for (int k = 0; k < 3; ++k) {
            int i = tid + k * 256;
            if (i < 720) {
                int r = i / 36, cl = i - r * 36;
                s_x[0][i] = x[((size_t)b * 32 * H_ + refl(h0 - 2 + r, H_)) * W_ + refl(w0 - 2 + cl, W_)];
            }
        }
#pragma unroll
        for (int k = 0; k < 6; ++k) {
            int i = tid + k * 256;
            if (i < 1440) {
                int br = i / 288, rem = i - br * 288;
                int tap = rem >> 5, co = rem & 31;
                s_w[0][i] = wgt[((size_t)co * 160 + br * 32) * 9 + tap];
            }
        }
    }
    __syncthreads();

    u64 acc[4][8];
#pragma unroll
    for (int j = 0; j < 8; ++j) {
        u64 bv = pk2(bias[ch * 16 + 2 * j], bias[ch * 16 + 2 * j + 1]);
#pragma unroll
        for (int p = 0; p < 4; ++p) acc[p][j] = bv;
    }

    int buf = 0;
    for (int ci = 0; ci < 32; ++ci) {
        const bool more = (ci + 1 < 32);
        float rx[3], rw[6];
        if (more) {
#pragma unroll
            for (int k = 0; k < 3; ++k) {
                int i = tid + k * 256;
                if (i < 720) {
                    int r = i / 36, cl = i - r * 36;
                    rx[k] = x[(((size_t)b * 32 + ci + 1) * H_ + refl(h0 - 2 + r, H_)) * W_ + refl(w0 - 2 + cl, W_)];
                }
            }
#pragma unroll
            for (int k = 0; k < 6; ++k) {
                int i = tid + k * 256;
                if (i < 1440) {
                    int br = i / 288, rem = i - br * 288;
                    int tap = rem >> 5, co = rem & 31;
                    rw[k] = wgt[((size_t)co * 160 + br * 32 + ci + 1) * 9 + tap];
                }
            }
        }
        // generate normalized operator tiles from s_x[buf]
        for (int i = tid; i < 612; i += 256) {
            int r = i / 34, cl = i - r * 34;
            int gh = h0 - 1 + r, gw = w0 - 1 + cl;
            float o[5] = {0.f, 0.f, 0.f, 0.f, 0.f};
            if (gh >= 0 && gh < H_ && gw >= 0 && gw < W_) {
                const float* p0 = &s_x[buf][r * 36 + cl];
                edge5(p0[0], p0[1], p0[2], p0[36], p0[37], p0[38], p0[72], p0[73], p0[74], o);
#pragma unroll
                for (int k = 0; k < 5; ++k) o[k] = (o[k] - s_nm[k]) * s_ns[k];
            }
#pragma unroll
            for (int k = 0; k < 5; ++k) s_op[k * 612 + i] = o[k];
        }
        __syncthreads();

        // FMA over 5 branch channels
#pragma unroll
        for (int br = 0; br < 5; ++br) {
            const float* ib = s_op + br * 612 + (gr * 4) * 34 + tx;
            const float* wb = s_w[buf] + br * 288;
#pragma unroll
            for (int di = 0; di < 3; ++di)
#pragma unroll
                for (int dj = 0; dj < 3; ++dj) {
                    u64 vpk[4];
#pragma unroll
                    for (int p = 0; p < 4; ++p) vpk[p] = pk(ib[(p + di) * 34 + dj]);
                    const u64* wp = (const u64*)(wb + (di * 3 + dj) * 32) + ch * 8;
                    u64 q0 = wp[0], q1 = wp[1], q2 = wp[2], q3 = wp[3];
                    u64 q4 = wp[4], q5 = wp[5], q6 = wp[6], q7 = wp[7];
#pragma unroll
                    for (int p = 0; p < 4; ++p) {
                        u64 v = vpk[p];
                        fma2(acc[p][0], v, q0); fma2(acc[p][1], v, q1);
                        fma2(acc[p][2], v, q2); fma2(acc[p][3], v, q3);
                        fma2(acc[p][4], v, q4); fma2(acc[p][5], v, q5);
                        fma2(acc[p][6], v, q6); fma2(acc[p][7], v, q7);
                    }
                }
        }
        if (more) {
#pragma unroll
            for (int k = 0; k < 3; ++k) {
                int i = tid + k * 256;
                if (i < 720) s_x[buf ^ 1][i] = rx[k];
            }
#pragma unroll
            for (int k = 0; k < 6; ++k) {
                int i = tid + k * 256;
                if (i < 1440) s_w[buf ^ 1][i] = rw[k];
            }
        }
        __syncthreads();
        buf ^= 1;
    }

    // pooled epilogue: 2x2 max -> 256^2
    const size_t plane = (size_t)256 * 256;
#pragma unroll
    for (int pp = 0; pp < 2; ++pp) {
        int hp = (h0 + gr * 4 + 2 * pp) >> 1;
        size_t ob = ((size_t)b * 32 + ch * 16) * plane + (size_t)hp * 256 + ((w0 + tx) >> 1);
#pragma unroll
        for (int j = 0; j < 8; ++j) {
            float lo0, hi0, lo1, hi1;
            unpk(acc[2 * pp][j], lo0, hi0);
            unpk(acc[2 * pp + 1][j], lo1, hi1);
            float m0 = fmaxf(lo0, lo1), m1 = fmaxf(hi0, hi1);
            m0 = fmaxf(m0, __shfl_xor_sync(0xffffffffu, m0, 1));
            m1 = fmaxf(m1, __shfl_xor_sync(0xffffffffu, m1, 1));
            if (!(tx & 1)) {
                out[ob + (size_t)(2 * j) * plane] = m0;
                out[ob + (size_t)(2 * j + 1) * plane] = m1;
            }
        }
    }
}

// ---------------- conv3x3 CIN=32 (zero pad), pipelined, f32x2 ----------------
// MODE 0: plain; MODE 1: fused 2x2 maxpool output; MODE 2: orig*y epilogue
// grid: (Ww/32, Hh/(4P), B), block: (32, 8)
template <int P, int MODE>
__global__ void __launch_bounds__(256, 2)
conv3x3_kernel(const float* __restrict__ in, const float* __restrict__ wgt,
               const float* __restrict__ bias, float* __restrict__ out,
               int Hh, int Ww, const float* __restrict__ orig) {
    constexpr int TH = 4 * P;
    constexpr int INR = TH + 2;
    constexpr int CH = 4 * INR * 34;
    constexpr int NPF = (CH + 255) / 256;
    __shared__ __align__(16) float s_in[2][CH];
    __shared__ __align__(16) float s_w[32 * 288];

    const int tx = threadIdx.x, ty = threadIdx.y;
    const int tid = ty * 32 + tx;
    const int w0 = blockIdx.x * 32, h0 = blockIdx.y * TH;
    const int b = blockIdx.z;
    const int gr = ty & 3, ch = ty >> 2;

    for (int i = tid; i < 32 * 288; i += 256) {
        int ci = i / 288, rem = i - ci * 288;
        int tap = rem >> 5, co = rem & 31;
        s_w[i] = wgt[((size_t)co * 32 + ci) * 9 + tap];
    }

    // initial chunk 0
    {
#pragma unroll
        for (int k = 0; k < NPF; ++k) {
            int i = tid + k * 256;
            if (i < CH) {
                int cc = i / (INR * 34), rem = i - cc * (INR * 34);
                int r = rem / 34, cl = rem - r * 34;
                int gh = h0 - 1 + r, gw = w0 - 1 + cl;
                float v = 0.f;
                if (gh >= 0 && gh < Hh && gw >= 0 && gw < Ww)
                    v = in[(((size_t)b * 32 + cc) * Hh + gh) * Ww + gw];
                s_in[0][i] = v;
            }
        }
    }
    __syncthreads();

    u64 acc[P][8];
#pragma unroll
    for (int j = 0; j < 8; ++j) {
        u64 bv = pk2(bias[ch * 16 + 2 * j], bias[ch * 16 + 2 * j + 1]);
#pragma unroll
        for (int p = 0; p < P; ++p) acc[p][j] = bv;
    }

    int buf = 0;
    for (int ci0 = 0; ci0 < 32; ci0 += 4) {
        const bool more = (ci0 + 4 < 32);
        float pf[NPF];
        if (more) {
#pragma unroll
            for (int k = 0; k < NPF; ++k) {
                int i = tid + k * 256;
                if (i < CH) {
                    int cc = i / (INR * 34), rem = i - cc * (INR * 34);
                    int r = rem / 34, cl = rem - r * 34;
                    int gh = h0 - 1 + r, gw = w0 - 1 + cl;
                    float v = 0.f;
                    if (gh >= 0 && gh < Hh && gw >= 0 && gw < Ww)
                        v = in[(((size_t)b * 32 + ci0 + 4 + cc) * Hh + gh) * Ww + gw];
                    pf[k] = v;
                }
            }
        }

#pragma unroll
        for (int cc = 0; cc < 4; ++cc) {
            const float* ib = s_in[buf] + cc * (INR * 34) + (gr * P) * 34 + tx;
            const float* wb = s_w + (ci0 + cc) * 288;
#pragma unroll
            for (int di = 0; di < 3; ++di)
#pragma unroll
                for (int dj = 0; dj < 3; ++dj) {
                    u64 vpk[P];
#pragma unroll
                    for (int p = 0; p < P; ++p) vpk[p] = pk(ib[(p + di) * 34 + dj]);
                    const u64* wp = (const u64*)(wb + (di * 3 + dj) * 32) + ch * 8;
                    u64 q0 = wp[0], q1 = wp[1], q2 = wp[2], q3 = wp[3];
                    u64 q4 = wp[4], q5 = wp[5], q6 = wp[6], q7 = wp[7];
#pragma unroll
                    for (int p = 0; p < P; ++p) {
                        u64 v = vpk[p];
                        fma2(acc[p][0], v, q0); fma2(acc[p][1], v, q1);
                        fma2(acc[p][2], v, q2); fma2(acc[p][3], v, q3);
                        fma2(acc[p][4], v, q4); fma2(acc[p][5], v, q5);
                        fma2(acc[p][6], v, q6); fma2(acc[p][7], v, q7);
                    }
                }
        }
        if (more) {
#pragma unroll
            for (int k = 0; k < NPF; ++k) {
                int i = tid + k * 256;
                if (i < CH) s_in[buf ^ 1][i] = pf[k];
            }
        }
        __syncthreads();
        buf ^= 1;
    }

    if (MODE == 1) {
        // fused 2x2 maxpool output
        const int Hp = Hh >> 1, Wp = Ww >> 1;
        const size_t plane = (size_t)Hp * Wp;
#pragma unroll
        for (int pp = 0; pp < P / 2; ++pp) {
            int hp = (h0 + gr * P + 2 * pp) >> 1;
            size_t ob = ((size_t)b * 32 + ch * 16) * plane + (size_t)hp * Wp + ((w0 + tx) >> 1);
#pragma unroll
            for (int j = 0; j < 8; ++j) {
                float lo0, hi0, lo1, hi1;
                unpk(acc[2 * pp][j], lo0, hi0);
                unpk(acc[2 * pp + 1][j], lo1, hi1);
                float m0 = fmaxf(lo0, lo1), m1 = fmaxf(hi0, hi1);
                m0 = fmaxf(m0, __shfl_xor_sync(0xffffffffu, m0, 1));
                m1 = fmaxf(m1, __shfl_xor_sync(0xffffffffu, m1, 1));
                if (!(tx & 1)) {
                    out[ob + (size_t)(2 * j) * plane] = m0;
                    out[ob + (size_t)(2 * j + 1) * plane] = m1;
                }
            }
        }
    } else {
        const size_t plane = (size_t)Hh * Ww;
#pragma unroll
        for (int p = 0; p < P; ++p) {
            int h = h0 + gr * P + p;
            size_t ob = ((size_t)b * 32 + ch * 16) * plane + (size_t)h * Ww + (w0 + tx);
#pragma unroll
            for (int j = 0; j < 8; ++j) {
                float lo, hi;
                unpk(acc[p][j], lo, hi);
                if (MODE == 2) {
                    lo *= orig[ob + (size_t)(2 * j) * plane];
                    hi *= orig[ob + (size_t)(2 * j + 1) * plane];
                }
                out[ob + (size_t)(2 * j) * plane] = lo;
                out[ob + (size_t)(2 * j + 1) * plane] = hi;
            }
        }
    }
}

// ---------------- deconv 2x2 stride 2 ----------------
// grid: (Wi/32, 4, B*Hi), block: (32, 8)
__global__ void deconv_kernel(const float* __restrict__ in, const float* __restrict__ wgt,
                              const float* __restrict__ bias, float* __restrict__ out,
                              int Hi, int Wi) {
    __shared__ float sx[32][33];
    __shared__ __align__(16) float sw[32][8][4];
    const int tx = threadIdx.x, ty = threadIdx.y;
    const int tid = ty * 32 + tx;
    const int w0 = blockIdx.x * 32;
    const int oc0 = blockIdx.y * 8;
    const int bh = blockIdx.z;
    const int b = bh / Hi, h = bh % Hi;

    for (int i = tid; i < 1024; i += 256) {
        int ci = i >> 5, w = i & 31;
        sx[ci][w] = in[(((size_t)b * 32 + ci) * Hi + h) * Wi + (w0 + w)];
    }
    for (int i = tid; i < 1024; i += 256) {
        int ci = i >> 5, rem = i & 31;
        int ol = rem >> 2, pq = rem & 3;
        sw[ci][ol][pq] = wgt[(size_t)ci * 128 + (oc0 + ol) * 4 + pq];
    }
    __syncthreads();

    const int o = oc0 + ty;
    const float bv = bias[o];
    u64 a01 = pk2(bv, bv), a23 = pk2(bv, bv);
#pragma unroll
    for (int ci = 0; ci < 32; ++ci) {
        u64 v = pk(sx[ci][tx]);
        const u64* wq = (const u64*)&sw[ci][ty][0];
        fma2(a01, v, wq[0]);
        fma2(a23, v, wq[1]);
    }
    float a0, a1, a2, a3;
    unpk(a01, a0, a1); unpk(a23, a2, a3);
    const int Ho = 2 * Hi, Wo = 2 * Wi;
    size_t ob = (((size_t)b * 32 + o) * Ho + 2 * h) * (size_t)Wo + 2 * (w0 + tx);
    *(float2*)(out + ob) = make_float2(a0, a1);
    *(float2*)(out + ob + Wo) = make_float2(a2, a3);
}

// ---------------- host launch ----------------
extern "C" void kernel_launch(void* const* d_in, const int* in_sizes, int n_in,
                              void* d_out, int out_size) {
    const float* x = (const float*)d_in[0];
    const float* w1 = (const float*)d_in[1];   const float* b1 = (const float*)d_in[2];
    const float* w2 = (const float*)d_in[3];   const float* b2 = (const float*)d_in[4];
    const float* w3 = (const float*)d_in[5];   const float* b3 = (const float*)d_in[6];
    const float* w4 = (const float*)d_in[7];   const float* b4 = (const float*)d_in[8];
    const float* w5 = (const float*)d_in[9];   const float* b5 = (const float*)d_in[10];
    const float* w6 = (const float*)d_in[11];  const float* b6 = (const float*)d_in[12];
    const float* w7 = (const float*)d_in[13];  const float* b7 = (const float*)d_in[14];
    const float* dw1 = (const float*)d_in[15]; const float* db1 = (const float*)d_in[16];
    const float* dw2 = (const float*)d_in[17]; const float* db2 = (const float*)d_in[18];
    const float* dw3 = (const float*)d_in[19]; const float* db3 = (const float*)d_in[20];
    float* outp = (float*)d_out;

    void* p;
    cudaGetSymbolAddress(&p, g_t1);  float* t1 = (float*)p;
    cudaGetSymbolAddress(&p, g_s1);  float* s1 = (float*)p;
    cudaGetSymbolAddress(&p, g_s2);  float* s2 = (float*)p;
    cudaGetSymbolAddress(&p, g_q1);  float* q1 = (float*)p;
    cudaGetSymbolAddress(&p, g_q2);  float* q2 = (float*)p;
    cudaGetSymbolAddress(&p, g_e1);  float* e1 = (float*)p;
    cudaGetSymbolAddress(&p, g_e2);  float* e2 = (float*)p;

    dim3 blk(32, 8);

    // stats (fused operator recompute, deterministic two-stage)
    stats_op_kernel<<<dim3(16, 64, B_ * C_), blk>>>(x);
    stats2_kernel<<<20, 256>>>();

    // conv1 fused (op regen + norm + conv + pool) -> s1 (256^2)
    conv1_fused_kernel<<<dim3(16, 32, B_), blk>>>(x, w1, b1, s1);
    // conv2 + pool: s1 (256^2) -> q1 (128^2)
    conv3x3_kernel<4, 1><<<dim3(8, 16, B_), blk>>>(s1, w2, b2, q1, 256, 256, nullptr);
    // conv3 + pool: q1 (128^2) -> e1 (64^2)
    conv3x3_kernel<4, 1><<<dim3(4, 8, B_), blk>>>(q1, w3, b3, e1, 128, 128, nullptr);
    // conv4: e1 -> e2 (64^2)
    conv3x3_kernel<1, 0><<<dim3(2, 16, B_), blk>>>(e1, w4, b4, e2, 64, 64, nullptr);
    // deconv1: e2 -> q2 (128^2); conv5: q2 -> q1 (128^2)
    deconv_kernel<<<dim3(2, 4, B_ * 64), blk>>>(e2, dw1, db1, q2, 64, 64);
    conv3x3_kernel<2, 0><<<dim3(4, 16, B_), blk>>>(q2, w5, b5, q1, 128, 128, nullptr);
    // deconv2: q1 -> s2 (256^2); conv6: s2 -> s1 (256^2)
    deconv_kernel<<<dim3(4, 4, B_ * 128), blk>>>(q1, dw2, db2, s2, 128, 128);
    conv3x3_kernel<4, 0><<<dim3(8, 16, B_), blk>>>(s2, w6, b6, s1, 256, 256, nullptr);
    // deconv3: s1 -> t1 (512^2); conv7 (+ orig mul): t1 -> out
    deconv_kernel<<<dim3(8, 4, B_ * 256), blk>>>(s1, dw3, db3, t1, 256, 256);
    conv3x3_kernel<4, 2><<<dim3(16, 32, B_), blk>>>(t1, w7, b7, outp, 512, 512, x);
}